// round 8
// baseline (speedup 1.0000x reference)
#include <cuda_runtime.h>
#include <cstdint>
#include <cstddef>

// DynamicFC: out[b,o,h,w] = sum_i W[b,o,i] * X[b,i,h,w] + bias[b,o]
// B=64, Cin=Cout=512, HW=784, fp32.  Per-batch GEMM C[512,784] = W @ X + bias.
//
// R6: smaller CTA tile 64x112 (warp tile 16x56, acc=28 regs), 3-stage
// cp.async pipeline, __launch_bounds__(256,3) -> 3 CTAs/SM (24 warps/SM,
// 6/SMSP) with ~15 regs of ptxas scheduling slack. Both operands cvt.rna
// in-loop (no staging registers).

#define COUT 512
#define CIN  512
#define HW   784

#define BM 64
#define BN 112
#define BK 32
#define NSTAGES 3
#define NITERS (CIN / BK)     // 16

#define AST 36                // A smem row stride: bank (4g+tg), conflict-free
#define BST 120               // B smem row stride: bank (24tg+8j+g), conflict-free
#define A_STAGE (BM * AST)    // 2304 floats
#define B_STAGE (BK * BST)    // 3840 floats
#define SMEM_FLOATS (NSTAGES * (A_STAGE + B_STAGE))   // 18432 floats = 73728 B

__device__ __forceinline__ uint32_t smem_u32(const void* p) {
    uint32_t a;
    asm("{ .reg .u64 t; cvta.to.shared.u64 t, %1; cvt.u32.u64 %0, t; }"
        : "=r"(a) : "l"(p));
    return a;
}
__device__ __forceinline__ uint32_t f2tf32(float x) {
    uint32_t u;
    asm("cvt.rna.tf32.f32 %0, %1;" : "=r"(u) : "f"(x));
    return u;
}
__device__ __forceinline__ void cpasync16(uint32_t s, const void* g) {
    asm volatile("cp.async.cg.shared.global [%0], [%1], 16;" :: "r"(s), "l"(g));
}
__device__ __forceinline__ void mma1688(float* c, const uint32_t* a, const uint32_t* b) {
    asm volatile(
        "mma.sync.aligned.m16n8k8.row.col.f32.tf32.tf32.f32 "
        "{%0,%1,%2,%3}, {%4,%5,%6,%7}, {%8,%9}, {%0,%1,%2,%3};"
        : "+f"(c[0]), "+f"(c[1]), "+f"(c[2]), "+f"(c[3])
        : "r"(a[0]), "r"(a[1]), "r"(a[2]), "r"(a[3]), "r"(b[0]), "r"(b[1]));
}

__device__ __forceinline__ void fill_stage(int st, int tid, uint32_t sb,
                                           const float* __restrict__ Wb,
                                           const float* __restrict__ Xb, int n0) {
    const int buf = st % NSTAGES;
    const uint32_t aB = sb + buf * (A_STAGE * 4);
    const uint32_t bB = sb + NSTAGES * (A_STAGE * 4) + buf * (B_STAGE * 4);
    const int k0 = st * BK;
    // A: 64 rows x 32 k = 512 float4 chunks (2/thread)
#pragma unroll
    for (int i = 0; i < 2; i++) {
        const int c   = tid + i * 256;
        const int row = c >> 3;         // m (0..63)
        const int kb  = c & 7;          // k chunk
        cpasync16(aB + (row * AST + kb * 4) * 4,
                  Wb + (size_t)row * CIN + k0 + kb * 4);
    }
    // B: 32 k-rows x 112 cols = 896 float4 chunks
#pragma unroll
    for (int i = 0; i < 4; i++) {
        const int c = tid + i * 256;
        if (c < 896) {
            const int row = c / 28;
            const int ch  = c - row * 28;
            cpasync16(bB + (row * BST + ch * 4) * 4,
                      Xb + (size_t)(k0 + row) * HW + n0 + ch * 4);
        }
    }
    asm volatile("cp.async.commit_group;" ::: "memory");
}

__global__ __launch_bounds__(256, 3)
void dynfc_tf32_kernel(const float* __restrict__ input,
                       const float* __restrict__ weight,
                       const float* __restrict__ bias,
                       float* __restrict__ out)
{
    extern __shared__ float smem[];
    const uint32_t sb = smem_u32(smem);

    const int tid  = threadIdx.x;
    const int wid  = tid >> 5;
    const int lane = tid & 31;
    const int g    = lane >> 2;      // 0..7
    const int tg   = lane & 3;       // 0..3
    const int wm   = wid >> 1;       // 0..3 (m warps, 16 rows each)
    const int wn   = wid & 1;        // 0..1 (n warps, 56 cols each)

    const int b  = blockIdx.z;
    const int m0 = blockIdx.y * BM;
    const int n0 = blockIdx.x * BN;

    const float* Wb = weight + ((size_t)b * COUT + m0) * CIN;
    const float* Xb = input  + (size_t)b * CIN * HW;

    // Accumulators: 1 m-atom x 7 n-atoms x 4, bias folded into init.
    float acc[7][4];
    {
        const int r0 = m0 + wm * 16 + g;
        const float bv0 = bias[b * COUT + r0];
        const float bv1 = bias[b * COUT + r0 + 8];
#pragma unroll
        for (int j = 0; j < 7; j++) {
            acc[j][0] = bv0; acc[j][1] = bv0;
            acc[j][2] = bv1; acc[j][3] = bv1;
        }
    }

    // Prologue: fill stages 0, 1.
    for (int s = 0; s < NSTAGES - 1; s++) fill_stage(s, tid, sb, Wb, Xb, n0);

    for (int s = 0; s < NITERS; s++) {
        const int buf = s % NSTAGES;
        if (s < NITERS - 1) {
            asm volatile("cp.async.wait_group 1;" ::: "memory");
        } else {
            asm volatile("cp.async.wait_group 0;" ::: "memory");
        }
        __syncthreads();
        if (s + NSTAGES - 1 < NITERS) fill_stage(s + NSTAGES - 1, tid, sb, Wb, Xb, n0);

        const float* Aw = smem + buf * A_STAGE + (wm * 16) * AST;
        const float* Bw = smem + NSTAGES * A_STAGE + buf * B_STAGE + wn * 56;

#pragma unroll
        for (int ks = 0; ks < BK / 8; ks++) {
            uint32_t afrag[4];
            {
                const float* ap = Aw + g * AST + ks * 8 + tg;
                afrag[0] = f2tf32(ap[0]);
                afrag[1] = f2tf32(ap[8 * AST]);
                afrag[2] = f2tf32(ap[4]);
                afrag[3] = f2tf32(ap[8 * AST + 4]);
            }
            uint32_t bfrag[7][2];
#pragma unroll
            for (int j = 0; j < 7; j++) {
                const float* bp = Bw + (ks * 8 + tg) * BST + j * 8 + g;
                bfrag[j][0] = f2tf32(bp[0]);
                bfrag[j][1] = f2tf32(bp[4 * BST]);
            }
#pragma unroll
            for (int j = 0; j < 7; j++)
                mma1688(acc[j], afrag, bfrag[j]);
        }
        __syncthreads();
    }

    // Epilogue: direct float2 stores (cols 2tg, 2tg+1 contiguous).
    float* Cb = out + (size_t)b * COUT * HW;
    {
        const int r0 = m0 + wm * 16 + g;
#pragma unroll
        for (int j = 0; j < 7; j++) {
            const int col = n0 + wn * 56 + j * 8 + 2 * tg;
            float2 v0 = make_float2(acc[j][0], acc[j][1]);
            float2 v1 = make_float2(acc[j][2], acc[j][3]);
            *reinterpret_cast<float2*>(Cb + (size_t)r0 * HW + col)       = v0;
            *reinterpret_cast<float2*>(Cb + (size_t)(r0 + 8) * HW + col) = v1;
        }
    }
}

extern "C" void kernel_launch(void* const* d_in, const int* in_sizes, int n_in,
                              void* d_out, int out_size)
{
    const float* input  = (const float*)d_in[0];  // (64, 512, 28, 28)
    const float* weight = (const float*)d_in[1];  // (64, 512, 512, 1, 1)
    const float* bias   = (const float*)d_in[2];  // (64, 512)
    float* out = (float*)d_out;

    cudaFuncSetAttribute(dynfc_tf32_kernel,
                         cudaFuncAttributeMaxDynamicSharedMemorySize,
                         SMEM_FLOATS * 4);
    dim3 grid(HW / BN, COUT / BM, 64);            // (7, 8, 64) = 3584 CTAs
    dynfc_tf32_kernel<<<grid, 256, SMEM_FLOATS * 4>>>(input, weight, bias, out);
}

// round 9
// speedup vs baseline: 1.0993x; 1.0993x over previous
#include <cuda_runtime.h>
#include <cstdint>
#include <cstddef>

// DynamicFC: out[b,o,h,w] = sum_i W[b,o,i] * X[b,i,h,w] + bias[b,o]
// B=64, Cin=Cout=512, HW=784, fp32.  Per-batch GEMM C[512,784] = W @ X + bias.
//
// R7: R4 tile (128x112x32, 256 thr, warp 32x56, 2 CTAs/SM) with a leaner
// inner loop:
//  - B pre-rounded to tf32 at fill (LDG -> cvt.rna -> scatter STS.32) into a
//    k-paired smem layout: word = kb*904 + col*8 + 2*(k%4) + (k/4).
//    Inner loop reads each B fragment pair with ONE LDS.64, zero cvt.
//    col-stride 8 => LDS.64 conflict-free; kb-stride 904 (=8 mod 32) =>
//    scatter STS conflict-free.
//  - A via cp.async (3 buffers, prefetch distance 2) + in-loop cvt (8/ks).
// ~190 instr/warp-stage vs R4's ~300; regs ~110 (slack under the 128 cap).

#define COUT 512
#define CIN  512
#define HW   784

#define BM 128
#define BN 112
#define BK 32
#define NITERS (CIN / BK)     // 16

#define AST 36                          // A row stride (floats): banks 4g+tg
#define A_STAGE (BM * AST)              // 4608 floats = 18432 B
#define KBSTRIDE 904                    // B kb-block stride (words), 904%32==8
#define B_STAGE (4 * KBSTRIDE)          // 3616 floats = 14464 B
// smem: 3 A buffers then 2 B buffers
#define B_OFF (3 * A_STAGE)
#define SMEM_FLOATS (3 * A_STAGE + 2 * B_STAGE)   // 21056 floats = 84224 B

__device__ __forceinline__ uint32_t smem_u32(const void* p) {
    uint32_t a;
    asm("{ .reg .u64 t; cvta.to.shared.u64 t, %1; cvt.u32.u64 %0, t; }"
        : "=r"(a) : "l"(p));
    return a;
}
__device__ __forceinline__ uint32_t f2tf32(float x) {
    uint32_t u;
    asm("cvt.rna.tf32.f32 %0, %1;" : "=r"(u) : "f"(x));
    return u;
}
__device__ __forceinline__ void cpasync16(uint32_t s, const void* g) {
    asm volatile("cp.async.cg.shared.global [%0], [%1], 16;" :: "r"(s), "l"(g));
}
__device__ __forceinline__ void mma1688(float* c, const uint32_t* a, const uint32_t* b) {
    asm volatile(
        "mma.sync.aligned.m16n8k8.row.col.f32.tf32.tf32.f32 "
        "{%0,%1,%2,%3}, {%4,%5,%6,%7}, {%8,%9}, {%0,%1,%2,%3};"
        : "+f"(c[0]), "+f"(c[1]), "+f"(c[2]), "+f"(c[3])
        : "r"(a[0]), "r"(a[1]), "r"(a[2]), "r"(a[3]), "r"(b[0]), "r"(b[1]));
}

// ---- A fill: cp.async, 128 rows x 32 k = 1024 float4 (4/thread) ------------
__device__ __forceinline__ void fillA(int st, int tid, uint32_t sb,
                                      const float* __restrict__ Wb) {
    const uint32_t aB = sb + (st % 3) * (A_STAGE * 4);
    const int k0 = st * BK;
#pragma unroll
    for (int i = 0; i < 4; i++) {
        const int c   = tid + i * 256;
        const int row = c >> 3;
        const int kb  = c & 7;
        cpasync16(aB + (row * AST + kb * 4) * 4,
                  Wb + (size_t)row * CIN + k0 + kb * 4);
    }
    asm volatile("cp.async.commit_group;" ::: "memory");
}

// ---- B fill: LDG.128 (k = lane, 4 cols), later cvt + scatter STS.32 --------
// task q = tid + 256j (q < 896): k = q%32 = lane, chunk = q/32 = warp + 8j.
__device__ __forceinline__ void ldgB(int st, int tid, float4* r,
                                     const float* __restrict__ Xb, int n0) {
    const int k0 = st * BK;
    const int k  = tid & 31;
#pragma unroll
    for (int j = 0; j < 4; j++) {
        const int q = tid + j * 256;
        if (q < 896) {
            const int chunk = q >> 5;
            r[j] = *reinterpret_cast<const float4*>(
                Xb + (size_t)(k0 + k) * HW + n0 + chunk * 4);
        }
    }
}
__device__ __forceinline__ void stsB(int st, int tid, uint32_t sb, const float4* r) {
    const uint32_t bB = sb + (B_OFF + (st & 1) * B_STAGE) * 4;
    const int k  = tid & 31;
    const int kb = k >> 3, kk = k & 7;
    const uint32_t base = bB + (kb * KBSTRIDE + 2 * (kk & 3) + (kk >> 2)) * 4;
#pragma unroll
    for (int j = 0; j < 4; j++) {
        const int q = tid + j * 256;
        if (q < 896) {
            const int c0 = (q >> 5) * 4;
            asm volatile("st.shared.b32 [%0], %1;"
                         :: "r"(base + (c0 + 0) * 32), "r"(f2tf32(r[j].x)) : "memory");
            asm volatile("st.shared.b32 [%0], %1;"
                         :: "r"(base + (c0 + 1) * 32), "r"(f2tf32(r[j].y)) : "memory");
            asm volatile("st.shared.b32 [%0], %1;"
                         :: "r"(base + (c0 + 2) * 32), "r"(f2tf32(r[j].z)) : "memory");
            asm volatile("st.shared.b32 [%0], %1;"
                         :: "r"(base + (c0 + 3) * 32), "r"(f2tf32(r[j].w)) : "memory");
        }
    }
}

__global__ __launch_bounds__(256, 2)
void dynfc_tf32_kernel(const float* __restrict__ input,
                       const float* __restrict__ weight,
                       const float* __restrict__ bias,
                       float* __restrict__ out)
{
    extern __shared__ float smem[];
    const uint32_t sb = smem_u32(smem);

    const int tid  = threadIdx.x;
    const int wid  = tid >> 5;
    const int lane = tid & 31;
    const int g    = lane >> 2;      // 0..7
    const int tg   = lane & 3;       // 0..3
    const int wm   = wid >> 1;       // 0..3 (m warps, 32 rows)
    const int wn   = wid & 1;        // 0..1 (n warps, 56 cols)

    const int b  = blockIdx.z;
    const int m0 = blockIdx.y * BM;
    const int n0 = blockIdx.x * BN;

    const float* Wb = weight + ((size_t)b * COUT + m0) * CIN;
    const float* Xb = input  + (size_t)b * CIN * HW;

    // Accumulators: 2 m-atoms x 7 n-atoms x 4, bias folded into init.
    float acc[2][7][4];
#pragma unroll
    for (int am = 0; am < 2; am++) {
        const int r0 = m0 + wm * 32 + am * 16 + g;
        const float bv0 = bias[b * COUT + r0];
        const float bv1 = bias[b * COUT + r0 + 8];
#pragma unroll
        for (int j = 0; j < 7; j++) {
            acc[am][j][0] = bv0; acc[am][j][1] = bv0;
            acc[am][j][2] = bv1; acc[am][j][3] = bv1;
        }
    }

    float4 rB[4];

    // Prologue: A stages 0,1 async; B stage 0 direct; B stage 1 staged in regs.
    fillA(0, tid, sb, Wb);
    fillA(1, tid, sb, Wb);
    ldgB(0, tid, rB, Xb, n0);
    stsB(0, tid, sb, rB);
    ldgB(1, tid, rB, Xb, n0);
    asm volatile("cp.async.wait_group 1;" ::: "memory");   // A(0) landed
    __syncthreads();

    for (int s = 0; s < NITERS; s++) {
        if (s + 2 < NITERS) fillA(s + 2, tid, sb, Wb);

        const float* Aw = smem + (s % 3) * A_STAGE + (wm * 32) * AST;
        // B fragment base (bytes): per-thread, col = wn*56 + j*8 + g, pair at 2tg.
        const uint32_t bBase = sb + (B_OFF + (s & 1) * B_STAGE) * 4
                             + ((wn * 56 + g) * 8 + 2 * tg) * 4;

#pragma unroll
        for (int ks = 0; ks < BK / 8; ks++) {
            uint32_t afrag[2][4];
#pragma unroll
            for (int am = 0; am < 2; am++) {
                const float* ap = Aw + (am * 16 + g) * AST + ks * 8 + tg;
                afrag[am][0] = f2tf32(ap[0]);
                afrag[am][1] = f2tf32(ap[8 * AST]);
                afrag[am][2] = f2tf32(ap[4]);
                afrag[am][3] = f2tf32(ap[8 * AST + 4]);
            }
            uint32_t bfrag[7][2];
#pragma unroll
            for (int j = 0; j < 7; j++) {
                asm volatile("ld.shared.v2.b32 {%0,%1}, [%2];"
                             : "=r"(bfrag[j][0]), "=r"(bfrag[j][1])
                             : "r"(bBase + (ks * KBSTRIDE + j * 64) * 4));
            }
#pragma unroll
            for (int am = 0; am < 2; am++)
#pragma unroll
                for (int j = 0; j < 7; j++)
                    mma1688(acc[am][j], afrag[am], bfrag[j]);
        }

        if (s + 1 < NITERS) stsB(s + 1, tid, sb, rB);   // other B buffer
        if (s + 2 < NITERS) ldgB(s + 2, tid, rB, Xb, n0);
        if (s + 2 < NITERS) {
            asm volatile("cp.async.wait_group 1;" ::: "memory");  // A(s+1) done
        } else {
            asm volatile("cp.async.wait_group 0;" ::: "memory");
        }
        __syncthreads();
    }

    // Epilogue: direct float2 stores (cols 2tg, 2tg+1 contiguous).
    float* Cb = out + (size_t)b * COUT * HW;
#pragma unroll
    for (int am = 0; am < 2; am++) {
        const int r0 = m0 + wm * 32 + am * 16 + g;
#pragma unroll
        for (int j = 0; j < 7; j++) {
            const int col = n0 + wn * 56 + j * 8 + 2 * tg;
            float2 v0 = make_float2(acc[am][j][0], acc[am][j][1]);
            float2 v1 = make_float2(acc[am][j][2], acc[am][j][3]);
            *reinterpret_cast<float2*>(Cb + (size_t)r0 * HW + col)       = v0;
            *reinterpret_cast<float2*>(Cb + (size_t)(r0 + 8) * HW + col) = v1;
        }
    }
}

extern "C" void kernel_launch(void* const* d_in, const int* in_sizes, int n_in,
                              void* d_out, int out_size)
{
    const float* input  = (const float*)d_in[0];  // (64, 512, 28, 28)
    const float* weight = (const float*)d_in[1];  // (64, 512, 512, 1, 1)
    const float* bias   = (const float*)d_in[2];  // (64, 512)
    float* out = (float*)d_out;

    cudaFuncSetAttribute(dynfc_tf32_kernel,
                         cudaFuncAttributeMaxDynamicSharedMemorySize,
                         SMEM_FLOATS * 4);
    dim3 grid(HW / BN, COUT / BM, 64);            // (7, 4, 64)
    dynfc_tf32_kernel<<<grid, 256, SMEM_FLOATS * 4>>>(input, weight, bias, out);
}